// round 1
// baseline (speedup 1.0000x reference)
#include <cuda_runtime.h>
#include <math.h>

#define BDIM 8
#define NDIM 1024
#define DDIM 256
#define HDIM 8
#define UDIM 64
#define HU   512
#define ROWS (BDIM*NDIM)   // 8192

// Scratch (static device globals — no allocations allowed)
__device__ float g_feat [ROWS*HU];
__device__ float g_resid[ROWS*HU];
__device__ float g_aself[ROWS*HDIM];
__device__ float g_aneigh[ROWS*HDIM];

// ---------------------------------------------------------------------------
// Kernel A: fp32 GEMM, C = X[8192,256] @ W[256,512].
// blockIdx.z selects (kernel -> g_feat) or (kernel_residual -> g_resid).
// 128x128 tile, BK=16, 256 threads, 8x8 microtile per thread.
// ---------------------------------------------------------------------------
__global__ __launch_bounds__(256) void proj_gemm(const float* __restrict__ Xg,
                                                 const float* __restrict__ W0,
                                                 const float* __restrict__ W1)
{
    const float* W = (blockIdx.z == 0) ? W0 : W1;
    float*       C = (blockIdx.z == 0) ? g_feat : g_resid;

    __shared__ __align__(16) float As[16][132];  // transposed [k][m], +4 pad
    __shared__ __align__(16) float Bs[16][128];

    const int tid = threadIdx.x;
    const int bm  = blockIdx.y * 128;
    const int bn  = blockIdx.x * 128;
    const int tx  = tid & 15;
    const int ty  = tid >> 4;

    float acc[8][8];
#pragma unroll
    for (int i = 0; i < 8; i++)
#pragma unroll
        for (int j = 0; j < 8; j++) acc[i][j] = 0.f;

    for (int k0 = 0; k0 < DDIM; k0 += 16) {
        // load X tile: 128 rows x 16 cols, transpose into As[k][m]
#pragma unroll
        for (int i = 0; i < 2; i++) {
            int idx = tid * 2 + i;            // 0..511 float4s
            int r   = idx >> 2;               // row 0..127
            int c4  = (idx & 3) << 2;         // col group 0,4,8,12
            float4 v = *(const float4*)(Xg + (size_t)(bm + r) * DDIM + k0 + c4);
            As[c4 + 0][r] = v.x;
            As[c4 + 1][r] = v.y;
            As[c4 + 2][r] = v.z;
            As[c4 + 3][r] = v.w;
        }
        // load W tile: 16 rows x 128 cols
#pragma unroll
        for (int i = 0; i < 2; i++) {
            int idx = tid * 2 + i;            // 0..511 float4s
            int r   = idx >> 5;               // k row 0..15
            int c4  = (idx & 31) << 2;        // col 0..124 step 4
            *(float4*)&Bs[r][c4] =
                *(const float4*)(W + (size_t)(k0 + r) * HU + bn + c4);
        }
        __syncthreads();

#pragma unroll
        for (int kk = 0; kk < 16; kk++) {
            float a[8], b[8];
            *(float4*)(a)     = *(const float4*)&As[kk][ty * 8];
            *(float4*)(a + 4) = *(const float4*)&As[kk][ty * 8 + 4];
            *(float4*)(b)     = *(const float4*)&Bs[kk][tx * 8];
            *(float4*)(b + 4) = *(const float4*)&Bs[kk][tx * 8 + 4];
#pragma unroll
            for (int i = 0; i < 8; i++)
#pragma unroll
                for (int j = 0; j < 8; j++)
                    acc[i][j] = fmaf(a[i], b[j], acc[i][j]);
        }
        __syncthreads();
    }

#pragma unroll
    for (int i = 0; i < 8; i++) {
        size_t off = (size_t)(bm + ty * 8 + i) * HU + bn + tx * 8;
        *(float4*)(C + off)     = make_float4(acc[i][0], acc[i][1], acc[i][2], acc[i][3]);
        *(float4*)(C + off + 4) = make_float4(acc[i][4], acc[i][5], acc[i][6], acc[i][7]);
    }
}

// ---------------------------------------------------------------------------
// Kernel B: per-row additive-attention logits.
// attn_self[row,h] = sum_u f[row,h,u]*aks[h,u]; same for neigh.
// One block per row, 512 threads (one per unit), 64-thread group reduce.
// ---------------------------------------------------------------------------
__global__ __launch_bounds__(512) void attn_logits(const float* __restrict__ aks,
                                                   const float* __restrict__ akn)
{
    const int row = blockIdx.x;
    const int tid = threadIdx.x;

    float fv = g_feat[(size_t)row * HU + tid];
    float s  = fv * aks[tid];
    float nn = fv * akn[tid];
#pragma unroll
    for (int off = 16; off; off >>= 1) {
        s  += __shfl_xor_sync(0xffffffffu, s,  off);
        nn += __shfl_xor_sync(0xffffffffu, nn, off);
    }
    __shared__ float ps[16], pn[16];
    int warp = tid >> 5;
    if ((tid & 31) == 0) { ps[warp] = s; pn[warp] = nn; }
    __syncthreads();
    if (tid < HDIM) {
        g_aself [row * HDIM + tid] = ps[2 * tid] + ps[2 * tid + 1];
        g_aneigh[row * HDIM + tid] = pn[2 * tid] + pn[2 * tid + 1];
    }
}

// ---------------------------------------------------------------------------
// Kernel C: sparse masked softmax + neighborhood aggregation + epilogue.
// One block per (b,n) row. Masked entries in the reference get logit-1e10,
// whose exp underflows to exactly 0.0f, so restricting to edges is bit-exact.
// ---------------------------------------------------------------------------
__global__ __launch_bounds__(256) void gat_agg(const float* __restrict__ A,
                                               const float* __restrict__ bias,
                                               float* __restrict__ out)
{
    const int row  = blockIdx.x;      // b*1024 + n
    const int b    = row >> 10;
    const int tid  = threadIdx.x;
    const int lane = tid & 31;
    const int warp = tid >> 5;

    __shared__ int   nidx[NDIM];
    __shared__ float w[NDIM * HDIM];      // 32 KB: per-edge per-head weight
    __shared__ int   s_cnt;
    __shared__ float aself[HDIM];
    __shared__ float wred[8][HDIM];
    __shared__ float hval[HDIM];

    if (tid == 0) s_cnt = 0;
    if (tid < HDIM) aself[tid] = g_aself[row * HDIM + tid];
    __syncthreads();

    // ---- collect edges: A[b,n,:] is exactly 0.0/1.0 ----
    {
        float4 av = *(const float4*)(A + (size_t)row * NDIM + tid * 4);
        int base = tid * 4;
        if (av.x != 0.f) nidx[atomicAdd(&s_cnt, 1)] = base;
        if (av.y != 0.f) nidx[atomicAdd(&s_cnt, 1)] = base + 1;
        if (av.z != 0.f) nidx[atomicAdd(&s_cnt, 1)] = base + 2;
        if (av.w != 0.f) nidx[atomicAdd(&s_cnt, 1)] = base + 3;
    }
    __syncthreads();
    const int nnz = s_cnt;

    // ---- logits + per-head running max ----
    float lmax[HDIM];
#pragma unroll
    for (int h = 0; h < HDIM; h++) lmax[h] = -INFINITY;
    const float* an_b = g_aneigh + (size_t)b * NDIM * HDIM;
    for (int e = tid; e < nnz; e += 256) {
        int k = nidx[e];
        const float* an = an_b + k * HDIM;
#pragma unroll
        for (int h = 0; h < HDIM; h++) {
            float x = aself[h] + an[h];
            x = (x > 0.f) ? x : 0.2f * x;          // leaky_relu(0.2)
            w[e * HDIM + h] = x;
            lmax[h] = fmaxf(lmax[h], x);
        }
    }
#pragma unroll
    for (int h = 0; h < HDIM; h++)
#pragma unroll
        for (int off = 16; off; off >>= 1)
            lmax[h] = fmaxf(lmax[h], __shfl_xor_sync(0xffffffffu, lmax[h], off));
    if (lane == 0) {
#pragma unroll
        for (int h = 0; h < HDIM; h++) wred[warp][h] = lmax[h];
    }
    __syncthreads();
    if (tid < HDIM) {
        float m = wred[0][tid];
#pragma unroll
        for (int wp = 1; wp < 8; wp++) m = fmaxf(m, wred[wp][tid]);
        hval[tid] = m;
    }
    __syncthreads();
    float hm[HDIM];
#pragma unroll
    for (int h = 0; h < HDIM; h++) hm[h] = hval[h];

    // ---- exp + per-head sum ----
    float lsum[HDIM];
#pragma unroll
    for (int h = 0; h < HDIM; h++) lsum[h] = 0.f;
    for (int e = tid; e < nnz; e += 256) {
#pragma unroll
        for (int h = 0; h < HDIM; h++) {
            float v = __expf(w[e * HDIM + h] - hm[h]);
            w[e * HDIM + h] = v;
            lsum[h] += v;
        }
    }
#pragma unroll
    for (int h = 0; h < HDIM; h++)
#pragma unroll
        for (int off = 16; off; off >>= 1)
            lsum[h] += __shfl_xor_sync(0xffffffffu, lsum[h], off);
    if (lane == 0) {
#pragma unroll
        for (int h = 0; h < HDIM; h++) wred[warp][h] = lsum[h];
    }
    __syncthreads();
    if (tid < HDIM) {
        float s = 0.f;
#pragma unroll
        for (int wp = 0; wp < 8; wp++) s += wred[wp][tid];
        hval[tid] = 1.0f / s;
    }
    __syncthreads();
#pragma unroll
    for (int h = 0; h < HDIM; h++) hm[h] = hval[h];   // inverse sums now
    for (int e = tid; e < nnz; e += 256) {
#pragma unroll
        for (int h = 0; h < HDIM; h++) w[e * HDIM + h] *= hm[h];
    }
    __syncthreads();

    // ---- aggregate: out[row,u] = sum_e coef[e, h(u)] * f[b, k_e, u] ----
    const int u0 = tid, u1 = tid + 256;
    const int h0 = tid >> 6, h1 = h0 + 4;
    const float* fb = g_feat + (size_t)b * NDIM * HU;
    float acc0 = 0.f, acc1 = 0.f;
#pragma unroll 4
    for (int e = 0; e < nnz; e++) {
        int k = nidx[e];
        const float* fr = fb + (size_t)k * HU;
        acc0 = fmaf(w[e * HDIM + h0], fr[u0], acc0);
        acc1 = fmaf(w[e * HDIM + h1], fr[u1], acc1);
    }

    size_t o = (size_t)row * HU;
    float r0 = acc0 + g_resid[o + u0] + bias[u0];
    float r1 = acc1 + g_resid[o + u1] + bias[u1];
    out[o + u0] = (r0 > 0.f) ? r0 : 0.f;
    out[o + u1] = (r1 > 0.f) ? r1 : 0.f;
}

// ---------------------------------------------------------------------------
extern "C" void kernel_launch(void* const* d_in, const int* in_sizes, int n_in,
                              void* d_out, int out_size)
{
    const float* X    = (const float*)d_in[0];  // [8,1024,256]
    const float* A    = (const float*)d_in[1];  // [8,1024,1024]
    const float* Wk   = (const float*)d_in[2];  // [256,512]
    const float* Wr   = (const float*)d_in[3];  // [256,512]
    const float* aks  = (const float*)d_in[4];  // [8,64,1] -> flat 512
    const float* akn  = (const float*)d_in[5];  // [8,64,1] -> flat 512
    const float* bias = (const float*)d_in[6];  // [512]
    float*       out  = (float*)d_out;          // [8,1024,512]

    (void)in_sizes; (void)n_in; (void)out_size;

    dim3 g(HU / 128, ROWS / 128, 2);
    proj_gemm<<<g, 256>>>(X, Wk, Wr);
    attn_logits<<<ROWS, 512>>>(aks, akn);
    gat_agg<<<ROWS, 256>>>(A, bias, out);
}